// round 2
// baseline (speedup 1.0000x reference)
#include <cuda_runtime.h>

// CustomStrainEnergyLoss: mean over B of (trapz(y_pred - y_true, x, segments j < idx))^2
// Inputs (metadata order): y_pred [B*N] f32, y_true [B*N] f32, x_values [N] f32,
//                          fracture_idx [B] i32. Output: scalar f32.
//
// Element-weight reformulation: for row r with idx = clamp(fidx[r], 0, N-1),
//   integral = sum_{j=0}^{idx} w(j) * (y_pred[j] - y_true[j])
//   w(j) = 0.5 * ( (j>0 ? x[j]-x[j-1] : 0) + (j<idx ? x[j+1]-x[j] : 0) )
// Each y element is loaded exactly once, and only elements [0, idx] are touched.

#define THREADS 256

__global__ void zero_out_kernel(float* out) {
    out[0] = 0.0f;
}

__global__ __launch_bounds__(THREADS)
void strain_loss_kernel(const float* __restrict__ y_pred,
                        const float* __restrict__ y_true,
                        const float* __restrict__ x,
                        const int* __restrict__ fidx,
                        float* __restrict__ out,
                        int N, float inv_B) {
    const int r = blockIdx.x;
    int idx = fidx[r];
    idx = min(max(idx, 0), N - 1);
    const int n_el = idx + 1;  // elements 0..idx participate

    const float* __restrict__ p = y_pred + (size_t)r * N;
    const float* __restrict__ t = y_true + (size_t)r * N;

    float acc = 0.0f;

    // Vectorized main loop over full float4 groups of elements [0, n_el)
    const int nvec = n_el >> 2;
    const float4* __restrict__ p4 = (const float4*)p;
    const float4* __restrict__ t4 = (const float4*)t;

    for (int v = threadIdx.x; v < nvec; v += THREADS) {
        const int j0 = v << 2;
        float4 a = p4[v];
        float4 b = t4[v];

        // x neighborhood: x[j0-1 .. j0+4]; x is tiny (32KB) -> L1-resident
        float xm1 = (j0 > 0) ? x[j0 - 1] : 0.0f;
        float x0 = x[j0];
        float x1 = x[j0 + 1];
        float x2 = x[j0 + 2];
        float x3 = x[j0 + 3];

        // weights: left diff + right diff, halved.
        // For j in a full vector, j <= nvec*4-1 <= idx. Only j==idx drops the
        // right term (and only j==0 drops the left term).
        float w0 = 0.5f * ((j0 > 0 ? (x0 - xm1) : 0.0f) + (j0 < idx ? (x1 - x0) : 0.0f));
        float w1 = 0.5f * ((x1 - x0) + (j0 + 1 < idx ? (x2 - x1) : 0.0f));
        float w2 = 0.5f * ((x2 - x1) + (j0 + 2 < idx ? (x3 - x2) : 0.0f));
        float w3r = (j0 + 3 < idx) ? (x[j0 + 4] - x3) : 0.0f;
        float w3 = 0.5f * ((x3 - x2) + w3r);

        acc += w0 * (a.x - b.x);
        acc += w1 * (a.y - b.y);
        acc += w2 * (a.z - b.z);
        acc += w3 * (a.w - b.w);
    }

    // Scalar tail: elements [nvec*4, n_el)
    for (int j = (nvec << 2) + threadIdx.x; j < n_el; j += THREADS) {
        float left  = (j > 0)   ? (x[j] - x[j - 1]) : 0.0f;
        float right = (j < idx) ? (x[j + 1] - x[j]) : 0.0f;
        float w = 0.5f * (left + right);
        acc += w * (p[j] - t[j]);
    }

    // Block reduction: warp shuffle then shared memory
    #pragma unroll
    for (int off = 16; off > 0; off >>= 1)
        acc += __shfl_xor_sync(0xFFFFFFFFu, acc, off);

    __shared__ float warp_sums[THREADS / 32];
    const int lane = threadIdx.x & 31;
    const int wid  = threadIdx.x >> 5;
    if (lane == 0) warp_sums[wid] = acc;
    __syncthreads();

    if (wid == 0) {
        float s = (lane < THREADS / 32) ? warp_sums[lane] : 0.0f;
        #pragma unroll
        for (int off = 4; off > 0; off >>= 1)
            s += __shfl_xor_sync(0xFFFFFFFFu, s, off);
        if (lane == 0) {
            // err_sq for this row, pre-scaled by 1/B; accumulate into scalar out
            atomicAdd(out, s * s * inv_B);
        }
    }
}

extern "C" void kernel_launch(void* const* d_in, const int* in_sizes, int n_in,
                              void* d_out, int out_size) {
    const float* y_pred = (const float*)d_in[0];
    const float* y_true = (const float*)d_in[1];
    const float* x_vals = (const float*)d_in[2];
    const int*   fidx   = (const int*)d_in[3];
    float* out = (float*)d_out;

    const int B = in_sizes[3];             // fracture_idx has B elements
    const int N = in_sizes[2];             // x_values has N elements

    zero_out_kernel<<<1, 1>>>(out);
    strain_loss_kernel<<<B, THREADS>>>(y_pred, y_true, x_vals, fidx, out,
                                       N, 1.0f / (float)B);
}